// round 5
// baseline (speedup 1.0000x reference)
#include <cuda_runtime.h>
#include <cuda_bf16.h>
#include <cstdint>

// ---------------------------------------------------------------------------
// Problem constants
// ---------------------------------------------------------------------------
#define B_     256
#define L_     512
#define E_     256
#define TWO_E  512
#define NODES  1023
#define SB     (NODES * E_)
#define C_     5

// Node states as split bf16 planes: value = hi + lo (~16 mantissa bits).
__device__ __nv_bfloat16 g_shi[(size_t)B_ * NODES * E_];
__device__ __nv_bfloat16 g_slo[(size_t)B_ * NODES * E_];
// W split into bf16 hi/lo, row-major (256 x 512).
__device__ __nv_bfloat16 g_Whi[E_ * TWO_E];
__device__ __nv_bfloat16 g_Wlo[E_ * TWO_E];

// ---------------------------------------------------------------------------
// Helpers
// ---------------------------------------------------------------------------
__device__ __forceinline__ uint32_t smem_u32(const void* p) {
    uint32_t a;
    asm("{ .reg .u64 t; cvta.to.shared.u64 t, %1; cvt.u32.u64 %0, t; }" : "=r"(a) : "l"(p));
    return a;
}
__device__ __forceinline__ uint32_t pkbf(__nv_bfloat16 a, __nv_bfloat16 b) {
    return (uint32_t)__bfloat16_as_ushort(a) | ((uint32_t)__bfloat16_as_ushort(b) << 16);
}

#define CP16(dst, src) \
    asm volatile("cp.async.cg.shared.global [%0], [%1], 16;" :: "r"(dst), "l"(src))
#define CP_COMMIT() asm volatile("cp.async.commit_group;" ::: "memory")

#define LDSM_X4(r, addr)                                                        \
    asm volatile("ldmatrix.sync.aligned.m8n8.x4.shared.b16 {%0,%1,%2,%3}, [%4];" \
        : "=r"((r)[0]), "=r"((r)[1]), "=r"((r)[2]), "=r"((r)[3]) : "r"(addr))

#define MMA16816(acc, a, b)                                                     \
    asm volatile("mma.sync.aligned.m16n8k16.row.col.f32.bf16.bf16.f32 "         \
        "{%0,%1,%2,%3}, {%4,%5,%6,%7}, {%8,%9}, {%0,%1,%2,%3};"                 \
        : "+f"((acc)[0]), "+f"((acc)[1]), "+f"((acc)[2]), "+f"((acc)[3])        \
        : "r"((a)[0]), "r"((a)[1]), "r"((a)[2]), "r"((a)[3]),                   \
          "r"((b)[0]), "r"((b)[1]))

#define ROWB 80                       // smem row: 32 bf16 (64B) + 16B pad

// ---------------------------------------------------------------------------
// SMEM layout: BM=64 A rows, 256 B rows, 2 planes each, 4 stages.
// ---------------------------------------------------------------------------
#define OFF_AH 0
#define OFF_AL 5120                   // 64 * 80
#define OFF_BH 10240
#define OFF_BL 30720                  // + 256 * 80
#define STAGE  51200
#define SMB    (4 * STAGE)            // bias: 256 floats            (204800)
#define SMP    (SMB + 1024)           // P tile: 5 x 256 floats      (205824)
#define SMRED  (SMP + 5120)           // proj partials 64x4x5 floats (210944)
#define SMEM_TOTAL (SMRED + 5120)     // 216064

// ---------------------------------------------------------------------------
// W split kernel: fp32 -> (hi, lo) bf16
// ---------------------------------------------------------------------------
__global__ void wsplit_kernel(const float* __restrict__ W) {
    int i = blockIdx.x * 256 + threadIdx.x;
    float f = W[i];
    __nv_bfloat16 h = __float2bfloat16(f);
    g_Whi[i] = h;
    g_Wlo[i] = __float2bfloat16(f - __bfloat162float(h));
}

// ---------------------------------------------------------------------------
// Leaves: relu(emb[word]) -> hi/lo planes + fused projection (direct store)
// ---------------------------------------------------------------------------
__global__ __launch_bounds__(256)
void leaf_kernel(const int* __restrict__ words, const float* __restrict__ emb,
                 const float* __restrict__ P, const float* __restrict__ pb,
                 float* __restrict__ out) {
    __shared__ float Ps[C_ * E_];
    __shared__ float pbs[C_];
    for (int idx = threadIdx.x; idx < C_ * E_; idx += 256) Ps[idx] = P[idx];
    if (threadIdx.x < C_) pbs[threadIdx.x] = pb[threadIdx.x];
    __syncthreads();

    int r    = blockIdx.x * 8 + (threadIdx.x >> 5);
    int lane = threadIdx.x & 31;
    int w = __ldg(&words[r]);
    const float4* src = reinterpret_cast<const float4*>(emb + (size_t)w * E_);
    float4 v0 = src[lane * 2], v1 = src[lane * 2 + 1];
    float x[8] = {fmaxf(v0.x, 0.f), fmaxf(v0.y, 0.f), fmaxf(v0.z, 0.f), fmaxf(v0.w, 0.f),
                  fmaxf(v1.x, 0.f), fmaxf(v1.y, 0.f), fmaxf(v1.z, 0.f), fmaxf(v1.w, 0.f)};
    uint32_t hi[4], lo[4];
#pragma unroll
    for (int p = 0; p < 4; p++) {
        __nv_bfloat16 ha = __float2bfloat16(x[2 * p]), hb = __float2bfloat16(x[2 * p + 1]);
        hi[p] = pkbf(ha, hb);
        lo[p] = pkbf(__float2bfloat16(x[2 * p]     - __bfloat162float(ha)),
                     __float2bfloat16(x[2 * p + 1] - __bfloat162float(hb)));
    }
    int b = r >> 9, i = r & 511;
    size_t off = (size_t)b * SB + (size_t)i * E_ + lane * 8;
    *reinterpret_cast<uint4*>(g_shi + off) = make_uint4(hi[0], hi[1], hi[2], hi[3]);
    *reinterpret_cast<uint4*>(g_slo + off) = make_uint4(lo[0], lo[1], lo[2], lo[3]);

    float acc[C_];
#pragma unroll
    for (int c = 0; c < C_; c++) {
        const float* pc = &Ps[c * E_ + lane * 8];
        float s = 0.f;
#pragma unroll
        for (int t = 0; t < 8; t++) s = fmaf(x[t], pc[t], s);
        acc[c] = s;
    }
#pragma unroll
    for (int c = 0; c < C_; c++)
#pragma unroll
        for (int o = 16; o > 0; o >>= 1)
            acc[c] += __shfl_xor_sync(0xffffffffu, acc[c], o);
    if (lane == 0) {
        float* orow = out + ((size_t)b * NODES + i) * C_;
#pragma unroll
        for (int c = 0; c < C_; c++) orow[c] = acc[c] + pbs[c];
    }
}

// ---------------------------------------------------------------------------
// Compose GEMM (mma.sync bf16, split hi/lo, 3 products) + fused projection.
// CTA tile 64 x 256 (full N), 512 threads = 16 warps (4M x 4N), warp tile
// 16 x 64. 4-stage cp.async pipeline over K=512 in BK=32 chunks.
// Every output row is CTA-private -> projection via smem reduce, direct store.
// ---------------------------------------------------------------------------
__global__ __launch_bounds__(512, 1)
void mma_gemm(const float* __restrict__ bias, const float* __restrict__ P,
              const float* __restrict__ pb, float* __restrict__ out,
              int in_off, int out_off, int lg) {
    extern __shared__ char smem[];
    const uint32_t sb = smem_u32(smem);
    const int tid  = threadIdx.x;
    const int lane = tid & 31;
    const int warp = tid >> 5;
    const int warpM = warp & 3;      // 4 warps over M (16 rows each)
    const int warpN = warp >> 2;     // 4 warps over N (64 cols each)
    const int blockRow = blockIdx.x * 64;
    const int msk = (1 << lg) - 1;

    if (tid < 256)
        reinterpret_cast<float*>(smem + SMB)[tid] = bias[tid];
    for (int j = tid; j < C_ * 256; j += 512)
        reinterpret_cast<float*>(smem + SMP)[j] = P[j];

    // --- per-thread cp.async chunk descriptors (5 x 16B per stage) ---
    const __nv_bfloat16* srcs[5];
    uint32_t dsts[5];
#pragma unroll
    for (int j = 0; j < 5; j++) {
        int c = tid + 512 * j;
        if (c < 512) {                  // A: 64 rows x 64B x 2 planes
            int plane = c >> 8, row = (c >> 2) & 63, seg = c & 3;
            int gr = blockRow + row, ab = gr >> lg, ai = gr & msk;
            const __nv_bfloat16* g = plane ? g_slo : g_shi;
            srcs[j] = g + (size_t)ab * SB + (size_t)in_off * E_
                        + (size_t)ai * TWO_E + seg * 8;
            dsts[j] = (plane ? OFF_AL : OFF_AH) + row * ROWB + seg * 16;
        } else {                        // B: 256 W-rows x 64B x 2 planes
            int c2 = c - 512;
            int plane = c2 >> 10, row = (c2 >> 2) & 255, seg = c2 & 3;
            const __nv_bfloat16* g = plane ? g_Wlo : g_Whi;
            srcs[j] = g + (size_t)row * TWO_E + seg * 8;
            dsts[j] = (plane ? OFF_BL : OFF_BH) + row * ROWB + seg * 16;
        }
    }

#define ISSUE(it) do {                                              \
        uint32_t _base = sb + ((it) & 3) * STAGE;                   \
        int _k0 = (it) * 32;                                        \
        _Pragma("unroll")                                           \
        for (int _j = 0; _j < 5; _j++)                              \
            CP16(_base + dsts[_j], srcs[_j] + _k0);                 \
        CP_COMMIT();                                                \
    } while (0)

    ISSUE(0); ISSUE(1); ISSUE(2);

    float acc[8][4];
#pragma unroll
    for (int nt = 0; nt < 8; nt++)
#pragma unroll
        for (int q = 0; q < 4; q++) acc[nt][q] = 0.f;

    const int aRow     = warpM * 16 + ((lane >> 3) & 1) * 8 + (lane & 7);
    const int aColHalf = (lane >> 4);
    const int bRow     = warpN * 64 + ((lane >> 4) << 3) + (lane & 7);
    const int bColHalf = (lane >> 3) & 1;

    for (int it = 0; it < 16; ++it) {
        if (it <= 13)      asm volatile("cp.async.wait_group 2;" ::: "memory");
        else if (it == 14) asm volatile("cp.async.wait_group 1;" ::: "memory");
        else               asm volatile("cp.async.wait_group 0;" ::: "memory");
        __syncthreads();
        if (it + 3 < 16) ISSUE(it + 3);
        uint32_t base = sb + (it & 3) * STAGE;

#pragma unroll
        for (int kk = 0; kk < 2; kk++) {
            uint32_t Ah[4], Al[4], Bh[8][2], Bl[8][2];
            {
                uint32_t addr = base + (uint32_t)(aRow * ROWB
                              + (kk * 16 + aColHalf * 8) * 2);
                LDSM_X4(Ah, addr + OFF_AH);
                LDSM_X4(Al, addr + OFF_AL);
            }
#pragma unroll
            for (int ntp = 0; ntp < 4; ntp++) {
                uint32_t addr = base + (uint32_t)((bRow + ntp * 16) * ROWB
                              + (kk * 16 + bColHalf * 8) * 2);
                uint32_t r0[4], r1[4];
                LDSM_X4(r0, addr + OFF_BH);
                LDSM_X4(r1, addr + OFF_BL);
                Bh[2 * ntp][0] = r0[0]; Bh[2 * ntp][1] = r0[1];
                Bh[2 * ntp + 1][0] = r0[2]; Bh[2 * ntp + 1][1] = r0[3];
                Bl[2 * ntp][0] = r1[0]; Bl[2 * ntp][1] = r1[1];
                Bl[2 * ntp + 1][0] = r1[2]; Bl[2 * ntp + 1][1] = r1[3];
            }
#pragma unroll
            for (int nt = 0; nt < 8; nt++) {
                MMA16816(acc[nt], Ah, Bh[nt]);
                MMA16816(acc[nt], Ah, Bl[nt]);
                MMA16816(acc[nt], Al, Bh[nt]);
            }
        }
    }
#undef ISSUE

    // --- epilogue: +bias, relu, split hi/lo store, projection partials ---
    const float* sbias = reinterpret_cast<const float*>(smem + SMB);
    const float* Ps2   = reinterpret_cast<const float*>(smem + SMP);
    float* red         = reinterpret_cast<float*>(smem + SMRED);
    const int nOff = warpN * 64 + (lane & 3) * 2;
#pragma unroll
    for (int h = 0; h < 2; h++) {
        int rl = warpM * 16 + (lane >> 2) + 8 * h;
        int gro = blockRow + rl;
        int ob = gro >> lg, oi = gro & msk;
        size_t rowoff = (size_t)ob * SB + (size_t)(out_off + oi) * E_ + nOff;
        uint32_t* dh = reinterpret_cast<uint32_t*>(g_shi + rowoff);
        uint32_t* dl = reinterpret_cast<uint32_t*>(g_slo + rowoff);
        float p5[C_] = {0.f, 0.f, 0.f, 0.f, 0.f};
#pragma unroll
        for (int nt = 0; nt < 8; nt++) {
            float v0 = fmaxf(acc[nt][2 * h]     + sbias[nOff + nt * 8], 0.f);
            float v1 = fmaxf(acc[nt][2 * h + 1] + sbias[nOff + nt * 8 + 1], 0.f);
            __nv_bfloat16 h0 = __float2bfloat16(v0), h1 = __float2bfloat16(v1);
            dh[nt * 4] = pkbf(h0, h1);
            dl[nt * 4] = pkbf(__float2bfloat16(v0 - __bfloat162float(h0)),
                              __float2bfloat16(v1 - __bfloat162float(h1)));
            int cl = nOff + nt * 8;
#pragma unroll
            for (int c = 0; c < C_; c++)
                p5[c] += v0 * Ps2[c * 256 + cl] + v1 * Ps2[c * 256 + cl + 1];
        }
#pragma unroll
        for (int c = 0; c < C_; c++) {
            p5[c] += __shfl_xor_sync(0xffffffffu, p5[c], 1);
            p5[c] += __shfl_xor_sync(0xffffffffu, p5[c], 2);
        }
        if ((lane & 3) == 0) {
#pragma unroll
            for (int c = 0; c < C_; c++)
                red[(rl * 4 + warpN) * C_ + c] = p5[c];
        }
    }
    __syncthreads();

    // final projection reduce: one thread per output row
    if (tid < 64) {
        int gro = blockRow + tid;
        int ob = gro >> lg, oi = gro & msk;
        float* orow = out + ((size_t)ob * NODES + out_off + oi) * C_;
#pragma unroll
        for (int c = 0; c < C_; c++) {
            float s = __ldg(&pb[c]);
#pragma unroll
            for (int w = 0; w < 4; w++) s += red[(tid * 4 + w) * C_ + c];
            orow[c] = s;
        }
    }
}

// ---------------------------------------------------------------------------
// Launch
// ---------------------------------------------------------------------------
extern "C" void kernel_launch(void* const* d_in, const int* in_sizes, int n_in,
                              void* d_out, int out_size) {
    const int*   words = (const int*)  d_in[0];
    const float* emb   = (const float*)d_in[1];
    const float* W     = (const float*)d_in[2];
    const float* bias  = (const float*)d_in[3];
    const float* P     = (const float*)d_in[4];
    const float* pb    = (const float*)d_in[5];
    float*       out   = (float*)d_out;

    static bool attr_done = false;
    if (!attr_done) {
        cudaFuncSetAttribute(mma_gemm, cudaFuncAttributeMaxDynamicSharedMemorySize,
                             SMEM_TOTAL);
        attr_done = true;
    }

    wsplit_kernel<<<(E_ * TWO_E) / 256, 256>>>(W);
    leaf_kernel<<<(B_ * L_) / 8, 256>>>(words, emb, P, pb, out);

    int off = 0, n = L_;
    for (int l = 0; l < 9; l++) {
        int rpb = n >> 1;
        int lg  = 8 - l;
        int M   = B_ * rpb;
        mma_gemm<<<M / 64, 512, SMEM_TOTAL>>>(bias, P, pb, out, off, off + n, lg);
        off += n;
        n >>= 1;
    }
}

// round 6
// speedup vs baseline: 1.1920x; 1.1920x over previous
#include <cuda_runtime.h>
#include <cuda_bf16.h>
#include <cstdint>

// ---------------------------------------------------------------------------
// Problem constants
// ---------------------------------------------------------------------------
#define B_     256
#define L_     512
#define E_     256
#define TWO_E  512
#define NODES  1023
#define SB     (NODES * E_)
#define C_     5

// Node states as split bf16 planes: value = hi + lo (~16 mantissa bits).
__device__ __nv_bfloat16 g_shi[(size_t)B_ * NODES * E_];
__device__ __nv_bfloat16 g_slo[(size_t)B_ * NODES * E_];
// W split into bf16 hi/lo, row-major (256 x 512).
__device__ __nv_bfloat16 g_Whi[E_ * TWO_E];
__device__ __nv_bfloat16 g_Wlo[E_ * TWO_E];

// ---------------------------------------------------------------------------
// Helpers
// ---------------------------------------------------------------------------
__device__ __forceinline__ uint32_t smem_u32(const void* p) {
    uint32_t a;
    asm("{ .reg .u64 t; cvta.to.shared.u64 t, %1; cvt.u32.u64 %0, t; }" : "=r"(a) : "l"(p));
    return a;
}
__device__ __forceinline__ uint32_t pkbf(__nv_bfloat16 a, __nv_bfloat16 b) {
    return (uint32_t)__bfloat16_as_ushort(a) | ((uint32_t)__bfloat16_as_ushort(b) << 16);
}

#define CP16(dst, src) \
    asm volatile("cp.async.cg.shared.global [%0], [%1], 16;" :: "r"(dst), "l"(src))
#define CP_COMMIT() asm volatile("cp.async.commit_group;" ::: "memory")

#define LDSM_X4(r, addr)                                                        \
    asm volatile("ldmatrix.sync.aligned.m8n8.x4.shared.b16 {%0,%1,%2,%3}, [%4];" \
        : "=r"((r)[0]), "=r"((r)[1]), "=r"((r)[2]), "=r"((r)[3]) : "r"(addr))

#define MMA16816(acc, a, b)                                                     \
    asm volatile("mma.sync.aligned.m16n8k16.row.col.f32.bf16.bf16.f32 "         \
        "{%0,%1,%2,%3}, {%4,%5,%6,%7}, {%8,%9}, {%0,%1,%2,%3};"                 \
        : "+f"((acc)[0]), "+f"((acc)[1]), "+f"((acc)[2]), "+f"((acc)[3])        \
        : "r"((a)[0]), "r"((a)[1]), "r"((a)[2]), "r"((a)[3]),                   \
          "r"((b)[0]), "r"((b)[1]))

#define ROWB 80                       // smem row: 32 bf16 (64B) + 16B pad

// ---------------------------------------------------------------------------
// init_out: out[b, n, c] = pb[c]  (atomic targets accumulate onto this)
// ---------------------------------------------------------------------------
__global__ void init_out(const float* __restrict__ pb, float* __restrict__ out) {
    size_t idx = (size_t)blockIdx.x * 256 + threadIdx.x;
    if (idx < (size_t)B_ * NODES * C_)
        out[idx] = pb[idx % C_];
}

// ---------------------------------------------------------------------------
// W split kernel: fp32 -> (hi, lo) bf16
// ---------------------------------------------------------------------------
__global__ void wsplit_kernel(const float* __restrict__ W) {
    int i = blockIdx.x * 256 + threadIdx.x;
    float f = W[i];
    __nv_bfloat16 h = __float2bfloat16(f);
    g_Whi[i] = h;
    g_Wlo[i] = __float2bfloat16(f - __bfloat162float(h));
}

// ---------------------------------------------------------------------------
// Leaves: relu(emb[word]) -> hi/lo planes + fused projection (direct store)
// ---------------------------------------------------------------------------
__global__ __launch_bounds__(256)
void leaf_kernel(const int* __restrict__ words, const float* __restrict__ emb,
                 const float* __restrict__ P, const float* __restrict__ pb,
                 float* __restrict__ out) {
    __shared__ float Ps[C_ * E_];
    __shared__ float pbs[C_];
    for (int idx = threadIdx.x; idx < C_ * E_; idx += 256) Ps[idx] = P[idx];
    if (threadIdx.x < C_) pbs[threadIdx.x] = pb[threadIdx.x];
    __syncthreads();

    int r    = blockIdx.x * 8 + (threadIdx.x >> 5);
    int lane = threadIdx.x & 31;
    int w = __ldg(&words[r]);
    const float4* src = reinterpret_cast<const float4*>(emb + (size_t)w * E_);
    float4 v0 = src[lane * 2], v1 = src[lane * 2 + 1];
    float x[8] = {fmaxf(v0.x, 0.f), fmaxf(v0.y, 0.f), fmaxf(v0.z, 0.f), fmaxf(v0.w, 0.f),
                  fmaxf(v1.x, 0.f), fmaxf(v1.y, 0.f), fmaxf(v1.z, 0.f), fmaxf(v1.w, 0.f)};
    uint32_t hi[4], lo[4];
#pragma unroll
    for (int p = 0; p < 4; p++) {
        __nv_bfloat16 ha = __float2bfloat16(x[2 * p]), hb = __float2bfloat16(x[2 * p + 1]);
        hi[p] = pkbf(ha, hb);
        lo[p] = pkbf(__float2bfloat16(x[2 * p]     - __bfloat162float(ha)),
                     __float2bfloat16(x[2 * p + 1] - __bfloat162float(hb)));
    }
    int b = r >> 9, i = r & 511;
    size_t off = (size_t)b * SB + (size_t)i * E_ + lane * 8;
    *reinterpret_cast<uint4*>(g_shi + off) = make_uint4(hi[0], hi[1], hi[2], hi[3]);
    *reinterpret_cast<uint4*>(g_slo + off) = make_uint4(lo[0], lo[1], lo[2], lo[3]);

    float acc[C_];
#pragma unroll
    for (int c = 0; c < C_; c++) {
        const float* pc = &Ps[c * E_ + lane * 8];
        float s = 0.f;
#pragma unroll
        for (int t = 0; t < 8; t++) s = fmaf(x[t], pc[t], s);
        acc[c] = s;
    }
#pragma unroll
    for (int c = 0; c < C_; c++)
#pragma unroll
        for (int o = 16; o > 0; o >>= 1)
            acc[c] += __shfl_xor_sync(0xffffffffu, acc[c], o);
    if (lane == 0) {
        float* orow = out + ((size_t)b * NODES + i) * C_;
#pragma unroll
        for (int c = 0; c < C_; c++) orow[c] = acc[c] + pbs[c];
    }
}

// ---------------------------------------------------------------------------
// Compose GEMM (mma.sync bf16, split hi/lo, 3 products) + fused projection.
// CTA tile BM x 128 (grid.y = 2 covers N=256), 512 threads = 16 warps (4x4),
// warp tile (16*MT) x 32. 4-stage cp.async pipeline over K=512, BK=32.
// Template: BM in {128, 64}, MT = BM/64, NCH = cp chunks/thread, PLA = A plane.
// ---------------------------------------------------------------------------
template <int BM, int MT, int NCH, int PLA>
__global__ __launch_bounds__(512, 1)
void mma_gemm(const float* __restrict__ bias, const float* __restrict__ P,
              float* __restrict__ out, int in_off, int out_off, int lg) {
    constexpr int OFF_AH = 0;
    constexpr int OFF_AL = PLA;
    constexpr int OFF_BH = 2 * PLA;
    constexpr int OFF_BL = 2 * PLA + 10240;
    constexpr int STAGE  = 2 * PLA + 20480;
    constexpr int SMB    = 4 * STAGE;          // bias: 128 floats
    constexpr int SMP    = SMB + 512;          // P tile: 5 x 128 floats

    extern __shared__ char smem[];
    const uint32_t sb = smem_u32(smem);
    const int tid  = threadIdx.x;
    const int lane = tid & 31;
    const int warp = tid >> 5;
    const int warpM = warp & 3;      // 4 warps over M
    const int warpN = warp >> 2;     // 4 warps over N (32 cols each)
    const int blockRow = blockIdx.x * BM;
    const int colBase  = blockIdx.y * 128;
    const int msk = (1 << lg) - 1;

    if (tid < 128)
        reinterpret_cast<float*>(smem + SMB)[tid] = bias[colBase + tid];
    for (int j = tid; j < C_ * 128; j += 512)
        reinterpret_cast<float*>(smem + SMP)[j] = P[(j >> 7) * E_ + colBase + (j & 127)];

    // --- per-thread cp.async chunk descriptors (NCH x 16B per stage) ---
    const __nv_bfloat16* srcs[NCH];
    uint32_t dsts[NCH];
#pragma unroll
    for (int j = 0; j < NCH; j++) {
        int c = tid + 512 * j;
        if (c < BM * 8) {               // A: BM rows x 64B x 2 planes
            int plane = c / (BM * 4), row = (c >> 2) % BM, seg = c & 3;
            int gr = blockRow + row, ab = gr >> lg, ai = gr & msk;
            const __nv_bfloat16* g = plane ? g_slo : g_shi;
            srcs[j] = g + (size_t)ab * SB + (size_t)in_off * E_
                        + (size_t)ai * TWO_E + seg * 8;
            dsts[j] = (plane ? OFF_AL : OFF_AH) + row * ROWB + seg * 16;
        } else {                        // B: 128 W-rows x 64B x 2 planes
            int c2 = c - BM * 8;
            int plane = c2 >> 9, row = (c2 >> 2) & 127, seg = c2 & 3;
            const __nv_bfloat16* g = plane ? g_Wlo : g_Whi;
            srcs[j] = g + (size_t)(colBase + row) * TWO_E + seg * 8;
            dsts[j] = (plane ? OFF_BL : OFF_BH) + row * ROWB + seg * 16;
        }
    }

#define ISSUE(it) do {                                              \
        uint32_t _base = sb + ((it) & 3) * STAGE;                   \
        int _k0 = (it) * 32;                                        \
        _Pragma("unroll")                                           \
        for (int _j = 0; _j < NCH; _j++)                            \
            CP16(_base + dsts[_j], srcs[_j] + _k0);                 \
        CP_COMMIT();                                                \
    } while (0)

    ISSUE(0); ISSUE(1); ISSUE(2);

    float acc[MT][4][4];
#pragma unroll
    for (int mt = 0; mt < MT; mt++)
#pragma unroll
        for (int nt = 0; nt < 4; nt++)
#pragma unroll
            for (int q = 0; q < 4; q++) acc[mt][nt][q] = 0.f;

    const int aRow     = warpM * (16 * MT) + ((lane >> 3) & 1) * 8 + (lane & 7);
    const int aColHalf = (lane >> 4);
    const int bRow     = warpN * 32 + ((lane >> 4) << 3) + (lane & 7);
    const int bColHalf = (lane >> 3) & 1;

    for (int it = 0; it < 16; ++it) {
        if (it <= 13)      asm volatile("cp.async.wait_group 2;" ::: "memory");
        else if (it == 14) asm volatile("cp.async.wait_group 1;" ::: "memory");
        else               asm volatile("cp.async.wait_group 0;" ::: "memory");
        __syncthreads();
        if (it + 3 < 16) ISSUE(it + 3);
        uint32_t base = sb + (it & 3) * STAGE;

#pragma unroll
        for (int kk = 0; kk < 2; kk++) {
            uint32_t Ah[MT][4], Al[MT][4], Bh[4][2], Bl[4][2];
#pragma unroll
            for (int mt = 0; mt < MT; mt++) {
                uint32_t addr = base + (uint32_t)((aRow + mt * 16) * ROWB
                              + (kk * 16 + aColHalf * 8) * 2);
                LDSM_X4(Ah[mt], addr + OFF_AH);
                LDSM_X4(Al[mt], addr + OFF_AL);
            }
#pragma unroll
            for (int ntp = 0; ntp < 2; ntp++) {
                uint32_t addr = base + (uint32_t)((bRow + ntp * 16) * ROWB
                              + (kk * 16 + bColHalf * 8) * 2);
                uint32_t r0[4], r1[4];
                LDSM_X4(r0, addr + OFF_BH);
                LDSM_X4(r1, addr + OFF_BL);
                Bh[2 * ntp][0] = r0[0]; Bh[2 * ntp][1] = r0[1];
                Bh[2 * ntp + 1][0] = r0[2]; Bh[2 * ntp + 1][1] = r0[3];
                Bl[2 * ntp][0] = r1[0]; Bl[2 * ntp][1] = r1[1];
                Bl[2 * ntp + 1][0] = r1[2]; Bl[2 * ntp + 1][1] = r1[3];
            }
#pragma unroll
            for (int mt = 0; mt < MT; mt++)
#pragma unroll
                for (int nt = 0; nt < 4; nt++) {
                    MMA16816(acc[mt][nt], Ah[mt], Bh[nt]);
                    MMA16816(acc[mt][nt], Ah[mt], Bl[nt]);
                    MMA16816(acc[mt][nt], Al[mt], Bh[nt]);
                }
        }
    }
#undef ISSUE

    // --- epilogue: +bias, relu, split hi/lo store, fused partial projection ---
    const float* sbias = reinterpret_cast<const float*>(smem + SMB);
    const float* Ps2   = reinterpret_cast<const float*>(smem + SMP);
    const int nOff = warpN * 32 + (lane & 3) * 2;
#pragma unroll
    for (int mt = 0; mt < MT; mt++) {
#pragma unroll
        for (int h = 0; h < 2; h++) {
            int rl = warpM * (16 * MT) + mt * 16 + (lane >> 2) + 8 * h;
            int gro = blockRow + rl;
            int ob = gro >> lg, oi = gro & msk;
            size_t rowoff = (size_t)ob * SB + (size_t)(out_off + oi) * E_
                          + colBase + nOff;
            uint32_t* dh = reinterpret_cast<uint32_t*>(g_shi + rowoff);
            uint32_t* dl = reinterpret_cast<uint32_t*>(g_slo + rowoff);
            float p5[C_] = {0.f, 0.f, 0.f, 0.f, 0.f};
#pragma unroll
            for (int nt = 0; nt < 4; nt++) {
                float v0 = fmaxf(acc[mt][nt][2 * h]     + sbias[nOff + nt * 8], 0.f);
                float v1 = fmaxf(acc[mt][nt][2 * h + 1] + sbias[nOff + nt * 8 + 1], 0.f);
                __nv_bfloat16 h0 = __float2bfloat16(v0), h1 = __float2bfloat16(v1);
                dh[nt * 4] = pkbf(h0, h1);
                dl[nt * 4] = pkbf(__float2bfloat16(v0 - __bfloat162float(h0)),
                                  __float2bfloat16(v1 - __bfloat162float(h1)));
                int cl = nOff + nt * 8;
#pragma unroll
                for (int c = 0; c < C_; c++)
                    p5[c] += v0 * Ps2[c * 128 + cl] + v1 * Ps2[c * 128 + cl + 1];
            }
#pragma unroll
            for (int c = 0; c < C_; c++) {
                p5[c] += __shfl_xor_sync(0xffffffffu, p5[c], 1);
                p5[c] += __shfl_xor_sync(0xffffffffu, p5[c], 2);
            }
            if ((lane & 3) == 0) {
                float* orow = out + ((size_t)ob * NODES + out_off + oi) * C_;
#pragma unroll
                for (int c = 0; c < C_; c++) atomicAdd(&orow[c], p5[c]);
            }
        }
    }
}

// ---------------------------------------------------------------------------
// Launch
// ---------------------------------------------------------------------------
#define SM128_TOTAL (4 * 40960 + 512 + 2560)   // 166912
#define SM64_TOTAL  (4 * 30720 + 512 + 2560)   // 125952

extern "C" void kernel_launch(void* const* d_in, const int* in_sizes, int n_in,
                              void* d_out, int out_size) {
    const int*   words = (const int*)  d_in[0];
    const float* emb   = (const float*)d_in[1];
    const float* W     = (const float*)d_in[2];
    const float* bias  = (const float*)d_in[3];
    const float* P     = (const float*)d_in[4];
    const float* pb    = (const float*)d_in[5];
    float*       out   = (float*)d_out;

    static bool attr_done = false;
    if (!attr_done) {
        cudaFuncSetAttribute(mma_gemm<128, 2, 4, 10240>,
                             cudaFuncAttributeMaxDynamicSharedMemorySize, SM128_TOTAL);
        cudaFuncSetAttribute(mma_gemm<64, 1, 3, 5120>,
                             cudaFuncAttributeMaxDynamicSharedMemorySize, SM64_TOTAL);
        attr_done = true;
    }

    init_out<<<(B_ * NODES * C_ + 255) / 256, 256>>>(pb, out);
    wsplit_kernel<<<(E_ * TWO_E) / 256, 256>>>(W);
    leaf_kernel<<<(B_ * L_) / 8, 256>>>(words, emb, P, pb, out);

    int off = 0, n = L_;
    for (int l = 0; l < 9; l++) {
        int rpb = n >> 1;
        int lg  = 8 - l;
        int M   = B_ * rpb;
        if (l < 4) {
            dim3 grid(M / 128, 2);
            mma_gemm<128, 2, 4, 10240><<<grid, 512, SM128_TOTAL>>>(
                bias, P, out, off, off + n, lg);
        } else {
            dim3 grid(M / 64, 2);
            mma_gemm<64, 1, 3, 5120><<<grid, 512, SM64_TOTAL>>>(
                bias, P, out, off, off + n, lg);
        }
        off += n;
        n >>= 1;
    }
}

// round 7
// speedup vs baseline: 1.5827x; 1.3278x over previous
#include <cuda_runtime.h>
#include <cuda_fp16.h>
#include <cstdint>

// ---------------------------------------------------------------------------
// Problem constants
// ---------------------------------------------------------------------------
#define B_     256
#define L_     512
#define E_     256
#define TWO_E  512
#define NODES  1023
#define SB     (NODES * E_)
#define C_     5

// Node states: single fp16 plane (11-bit mantissa).
__device__ __half g_sh[(size_t)B_ * NODES * E_];
// W split into fp16 hi/lo, row-major (256 x 512): W ~= Whi + Wlo (~22 bits).
__device__ __half g_Whi[E_ * TWO_E];
__device__ __half g_Wlo[E_ * TWO_E];

// ---------------------------------------------------------------------------
// Helpers
// ---------------------------------------------------------------------------
__device__ __forceinline__ uint32_t smem_u32(const void* p) {
    uint32_t a;
    asm("{ .reg .u64 t; cvta.to.shared.u64 t, %1; cvt.u32.u64 %0, t; }" : "=r"(a) : "l"(p));
    return a;
}
__device__ __forceinline__ uint32_t pkh(__half a, __half b) {
    return (uint32_t)__half_as_ushort(a) | ((uint32_t)__half_as_ushort(b) << 16);
}

#define CP16(dst, src) \
    asm volatile("cp.async.cg.shared.global [%0], [%1], 16;" :: "r"(dst), "l"(src))
#define CP_COMMIT() asm volatile("cp.async.commit_group;" ::: "memory")

#define LDSM_X4(r, addr)                                                        \
    asm volatile("ldmatrix.sync.aligned.m8n8.x4.shared.b16 {%0,%1,%2,%3}, [%4];" \
        : "=r"((r)[0]), "=r"((r)[1]), "=r"((r)[2]), "=r"((r)[3]) : "r"(addr))

#define MMA16816(acc, a, b)                                                     \
    asm volatile("mma.sync.aligned.m16n8k16.row.col.f32.f16.f16.f32 "           \
        "{%0,%1,%2,%3}, {%4,%5,%6,%7}, {%8,%9}, {%0,%1,%2,%3};"                 \
        : "+f"((acc)[0]), "+f"((acc)[1]), "+f"((acc)[2]), "+f"((acc)[3])        \
        : "r"((a)[0]), "r"((a)[1]), "r"((a)[2]), "r"((a)[3]),                   \
          "r"((b)[0]), "r"((b)[1]))

#define ROWB 80                       // smem row: 32 halves (64B) + 16B pad

// ---------------------------------------------------------------------------
// init_out: out[b, n, c] = pb[c]  (atomic targets accumulate onto this)
// ---------------------------------------------------------------------------
__global__ void init_out(const float* __restrict__ pb, float* __restrict__ out) {
    size_t idx = (size_t)blockIdx.x * 256 + threadIdx.x;
    if (idx < (size_t)B_ * NODES * C_)
        out[idx] = pb[idx % C_];
}

// ---------------------------------------------------------------------------
// W split kernel: fp32 -> (hi, lo) fp16
// ---------------------------------------------------------------------------
__global__ void wsplit_kernel(const float* __restrict__ W) {
    int i = blockIdx.x * 256 + threadIdx.x;
    float f = W[i];
    __half h = __float2half_rn(f);
    g_Whi[i] = h;
    g_Wlo[i] = __float2half_rn(f - __half2float(h));
}

// ---------------------------------------------------------------------------
// Leaves: relu(emb[word]) -> fp16 state + fused projection (direct store)
// ---------------------------------------------------------------------------
__global__ __launch_bounds__(256)
void leaf_kernel(const int* __restrict__ words, const float* __restrict__ emb,
                 const float* __restrict__ P, const float* __restrict__ pb,
                 float* __restrict__ out) {
    __shared__ float Ps[C_ * E_];
    __shared__ float pbs[C_];
    for (int idx = threadIdx.x; idx < C_ * E_; idx += 256) Ps[idx] = P[idx];
    if (threadIdx.x < C_) pbs[threadIdx.x] = pb[threadIdx.x];
    __syncthreads();

    int r    = blockIdx.x * 8 + (threadIdx.x >> 5);
    int lane = threadIdx.x & 31;
    int w = __ldg(&words[r]);
    const float4* src = reinterpret_cast<const float4*>(emb + (size_t)w * E_);
    float4 v0 = src[lane * 2], v1 = src[lane * 2 + 1];
    float x[8] = {fmaxf(v0.x, 0.f), fmaxf(v0.y, 0.f), fmaxf(v0.z, 0.f), fmaxf(v0.w, 0.f),
                  fmaxf(v1.x, 0.f), fmaxf(v1.y, 0.f), fmaxf(v1.z, 0.f), fmaxf(v1.w, 0.f)};
    uint32_t hv[4];
#pragma unroll
    for (int p = 0; p < 4; p++)
        hv[p] = pkh(__float2half_rn(x[2 * p]), __float2half_rn(x[2 * p + 1]));
    int b = r >> 9, i = r & 511;
    size_t off = (size_t)b * SB + (size_t)i * E_ + lane * 8;
    *reinterpret_cast<uint4*>(g_sh + off) = make_uint4(hv[0], hv[1], hv[2], hv[3]);

    float acc[C_];
#pragma unroll
    for (int c = 0; c < C_; c++) {
        const float* pc = &Ps[c * E_ + lane * 8];
        float s = 0.f;
#pragma unroll
        for (int t = 0; t < 8; t++) s = fmaf(x[t], pc[t], s);
        acc[c] = s;
    }
#pragma unroll
    for (int c = 0; c < C_; c++)
#pragma unroll
        for (int o = 16; o > 0; o >>= 1)
            acc[c] += __shfl_xor_sync(0xffffffffu, acc[c], o);
    if (lane == 0) {
        float* orow = out + ((size_t)b * NODES + i) * C_;
#pragma unroll
        for (int c = 0; c < C_; c++) orow[c] = acc[c] + pbs[c];
    }
}

// ---------------------------------------------------------------------------
// Compose GEMM (mma.sync fp16, 2 products: Xhi*Whi + Xhi*Wlo) + fused proj.
// CTA tile BM x 128 (grid.y = 2 covers N=256), 512 threads = 16 warps (4x4),
// warp tile (16*MT) x 32. 4-stage cp.async pipeline over K=512, BK=32.
// ---------------------------------------------------------------------------
template <int BM, int MT, int NCH, int TOTCH, int PLA>
__global__ __launch_bounds__(512, 1)
void mma_gemm(const float* __restrict__ bias, const float* __restrict__ P,
              float* __restrict__ out, int in_off, int out_off, int lg) {
    constexpr int OFF_AH = 0;
    constexpr int OFF_BH = PLA;
    constexpr int OFF_BL = PLA + 10240;
    constexpr int STAGE  = PLA + 20480;
    constexpr int SMB    = 4 * STAGE;          // bias: 128 floats
    constexpr int SMP    = SMB + 512;          // P tile: 5 x 128 floats

    extern __shared__ char smem[];
    const uint32_t sb = smem_u32(smem);
    const int tid  = threadIdx.x;
    const int lane = tid & 31;
    const int warp = tid >> 5;
    const int warpM = warp & 3;      // 4 warps over M
    const int warpN = warp >> 2;     // 4 warps over N (32 cols each)
    const int blockRow = blockIdx.x * BM;
    const int colBase  = blockIdx.y * 128;
    const int msk = (1 << lg) - 1;

    if (tid < 128)
        reinterpret_cast<float*>(smem + SMB)[tid] = bias[colBase + tid];
    for (int j = tid; j < C_ * 128; j += 512)
        reinterpret_cast<float*>(smem + SMP)[j] = P[(j >> 7) * E_ + colBase + (j & 127)];

    // --- per-thread cp.async chunk descriptors (<= NCH x 16B per stage) ---
    const __half* srcs[NCH];
    uint32_t dsts[NCH];
#pragma unroll
    for (int j = 0; j < NCH; j++) {
        int c = tid + 512 * j;
        if (c >= TOTCH) c = TOTCH - 1;  // harmless duplicate (guarded at issue)
        if (c < BM * 4) {               // A: BM rows x 64B x 1 plane
            int row = c >> 2, seg = c & 3;
            int gr = blockRow + row, ab = gr >> lg, ai = gr & msk;
            srcs[j] = g_sh + (size_t)ab * SB + (size_t)in_off * E_
                          + (size_t)ai * TWO_E + seg * 8;
            dsts[j] = OFF_AH + row * ROWB + seg * 16;
        } else {                        // B: 128 W-rows x 64B x 2 planes
            int c2 = c - BM * 4;
            int plane = c2 >> 9, row = (c2 >> 2) & 127, seg = c2 & 3;
            const __half* g = plane ? g_Wlo : g_Whi;
            srcs[j] = g + (size_t)(colBase + row) * TWO_E + seg * 8;
            dsts[j] = (plane ? OFF_BL : OFF_BH) + row * ROWB + seg * 16;
        }
    }

#define ISSUE(it) do {                                              \
        uint32_t _base = sb + ((it) & 3) * STAGE;                   \
        int _k0 = (it) * 32;                                        \
        _Pragma("unroll")                                           \
        for (int _j = 0; _j < NCH; _j++)                            \
            if (tid + 512 * _j < TOTCH)                             \
                CP16(_base + dsts[_j], srcs[_j] + _k0);             \
        CP_COMMIT();                                                \
    } while (0)

    ISSUE(0); ISSUE(1); ISSUE(2);

    float acc[MT][4][4];
#pragma unroll
    for (int mt = 0; mt < MT; mt++)
#pragma unroll
        for (int nt = 0; nt < 4; nt++)
#pragma unroll
            for (int q = 0; q < 4; q++) acc[mt][nt][q] = 0.f;

    const int aRow     = warpM * (16 * MT) + ((lane >> 3) & 1) * 8 + (lane & 7);
    const int aColHalf = (lane >> 4);
    const int bRow     = warpN * 32 + ((lane >> 4) << 3) + (lane & 7);
    const int bColHalf = (lane >> 3) & 1;

    for (int it = 0; it < 16; ++it) {
        if (it <= 13)      asm volatile("cp.async.wait_group 2;" ::: "memory");
        else if (it == 14) asm volatile("cp.async.wait_group 1;" ::: "memory");
        else               asm volatile("cp.async.wait_group 0;" ::: "memory");
        __syncthreads();
        if (it + 3 < 16) ISSUE(it + 3);
        uint32_t base = sb + (it & 3) * STAGE;

#pragma unroll
        for (int kk = 0; kk < 2; kk++) {
            uint32_t Ah[MT][4], Bh[4][2], Bl[4][2];
#pragma unroll
            for (int mt = 0; mt < MT; mt++) {
                uint32_t addr = base + (uint32_t)((aRow + mt * 16) * ROWB
                              + (kk * 16 + aColHalf * 8) * 2);
                LDSM_X4(Ah[mt], addr + OFF_AH);
            }
#pragma unroll
            for (int ntp = 0; ntp < 2; ntp++) {
                uint32_t addr = base + (uint32_t)((bRow + ntp * 16) * ROWB
                              + (kk * 16 + bColHalf * 8) * 2);
                uint32_t r0[4], r1[4];
                LDSM_X4(r0, addr + OFF_BH);
                LDSM_X4(r1, addr + OFF_BL);
                Bh[2 * ntp][0] = r0[0]; Bh[2 * ntp][1] = r0[1];
                Bh[2 * ntp + 1][0] = r0[2]; Bh[2 * ntp + 1][1] = r0[3];
                Bl[2 * ntp][0] = r1[0]; Bl[2 * ntp][1] = r1[1];
                Bl[2 * ntp + 1][0] = r1[2]; Bl[2 * ntp + 1][1] = r1[3];
            }
#pragma unroll
            for (int mt = 0; mt < MT; mt++)
#pragma unroll
                for (int nt = 0; nt < 4; nt++) {
                    MMA16816(acc[mt][nt], Ah[mt], Bh[nt]);
                    MMA16816(acc[mt][nt], Ah[mt], Bl[nt]);
                }
        }
    }
#undef ISSUE

    // --- epilogue: +bias, relu, fp16 state store, fused partial projection ---
    const float* sbias = reinterpret_cast<const float*>(smem + SMB);
    const float* Ps2   = reinterpret_cast<const float*>(smem + SMP);
    const int nOff = warpN * 32 + (lane & 3) * 2;
#pragma unroll
    for (int mt = 0; mt < MT; mt++) {
#pragma unroll
        for (int h = 0; h < 2; h++) {
            int rl = warpM * (16 * MT) + mt * 16 + (lane >> 2) + 8 * h;
            int gro = blockRow + rl;
            int ob = gro >> lg, oi = gro & msk;
            size_t rowoff = (size_t)ob * SB + (size_t)(out_off + oi) * E_
                          + colBase + nOff;
            uint32_t* dh = reinterpret_cast<uint32_t*>(g_sh + rowoff);
            float p5[C_] = {0.f, 0.f, 0.f, 0.f, 0.f};
#pragma unroll
            for (int nt = 0; nt < 4; nt++) {
                float v0 = fmaxf(acc[mt][nt][2 * h]     + sbias[nOff + nt * 8], 0.f);
                float v1 = fmaxf(acc[mt][nt][2 * h + 1] + sbias[nOff + nt * 8 + 1], 0.f);
                dh[nt * 4] = pkh(__float2half_rn(v0), __float2half_rn(v1));
                int cl = nOff + nt * 8;
#pragma unroll
                for (int c = 0; c < C_; c++)
                    p5[c] += v0 * Ps2[c * 128 + cl] + v1 * Ps2[c * 128 + cl + 1];
            }
#pragma unroll
            for (int c = 0; c < C_; c++) {
                p5[c] += __shfl_xor_sync(0xffffffffu, p5[c], 1);
                p5[c] += __shfl_xor_sync(0xffffffffu, p5[c], 2);
            }
            if ((lane & 3) == 0) {
                float* orow = out + ((size_t)ob * NODES + out_off + oi) * C_;
#pragma unroll
                for (int c = 0; c < C_; c++) atomicAdd(&orow[c], p5[c]);
            }
        }
    }
}

// ---------------------------------------------------------------------------
// Launch
// ---------------------------------------------------------------------------
#define SM128_TOTAL (4 * 30720 + 512 + 2560)   // 125952
#define SM64_TOTAL  (4 * 25600 + 512 + 2560)   // 105472

extern "C" void kernel_launch(void* const* d_in, const int* in_sizes, int n_in,
                              void* d_out, int out_size) {
    const int*   words = (const int*)  d_in[0];
    const float* emb   = (const float*)d_in[1];
    const float* W     = (const float*)d_in[2];
    const float* bias  = (const float*)d_in[3];
    const float* P     = (const float*)d_in[4];
    const float* pb    = (const float*)d_in[5];
    float*       out   = (float*)d_out;

    static bool attr_done = false;
    if (!attr_done) {
        cudaFuncSetAttribute((const void*)mma_gemm<128, 2, 3, 1536, 10240>,
                             cudaFuncAttributeMaxDynamicSharedMemorySize, SM128_TOTAL);
        cudaFuncSetAttribute((const void*)mma_gemm<64, 1, 3, 1280, 5120>,
                             cudaFuncAttributeMaxDynamicSharedMemorySize, SM64_TOTAL);
        attr_done = true;
    }

    init_out<<<(B_ * NODES * C_ + 255) / 256, 256>>>(pb, out);
    wsplit_kernel<<<(E_ * TWO_E) / 256, 256>>>(W);
    leaf_kernel<<<(B_ * L_) / 8, 256>>>(words, emb, P, pb, out);

    int off = 0, n = L_;
    for (int l = 0; l < 9; l++) {
        int rpb = n >> 1;
        int lg  = 8 - l;
        int M   = B_ * rpb;
        if (l < 4) {
            dim3 grid(M / 128, 2);
            mma_gemm<128, 2, 3, 1536, 10240><<<grid, 512, SM128_TOTAL>>>(
                bias, P, out, off, off + n, lg);
        } else {
            dim3 grid(M / 64, 2);
            mma_gemm<64, 1, 3, 1280, 5120><<<grid, 512, SM64_TOTAL>>>(
                bias, P, out, off, off + n, lg);
        }
        off += n;
        n >>= 1;
    }
}

// round 8
// speedup vs baseline: 2.3351x; 1.4754x over previous
#include <cuda_runtime.h>
#include <cuda_fp16.h>
#include <cstdint>

// ---------------------------------------------------------------------------
// Problem constants
// ---------------------------------------------------------------------------
#define B_     256
#define L_     512
#define E_     256
#define TWO_E  512
#define NODES  1023
#define SB     (NODES * E_)
#define C_     5

// Node states: single fp16 plane (11-bit mantissa).
__device__ __half g_sh[(size_t)B_ * NODES * E_];
// W as fp16, row-major (256 x 512).
__device__ __half g_Wh[E_ * TWO_E];

// ---------------------------------------------------------------------------
// Helpers
// ---------------------------------------------------------------------------
__device__ __forceinline__ uint32_t smem_u32(const void* p) {
    uint32_t a;
    asm("{ .reg .u64 t; cvta.to.shared.u64 t, %1; cvt.u32.u64 %0, t; }" : "=r"(a) : "l"(p));
    return a;
}
__device__ __forceinline__ uint32_t pkh(__half a, __half b) {
    return (uint32_t)__half_as_ushort(a) | ((uint32_t)__half_as_ushort(b) << 16);
}

#define CP16(dst, src) \
    asm volatile("cp.async.cg.shared.global [%0], [%1], 16;" :: "r"(dst), "l"(src))
#define CP_COMMIT() asm volatile("cp.async.commit_group;" ::: "memory")

#define LDSM_X4(r, addr)                                                        \
    asm volatile("ldmatrix.sync.aligned.m8n8.x4.shared.b16 {%0,%1,%2,%3}, [%4];" \
        : "=r"((r)[0]), "=r"((r)[1]), "=r"((r)[2]), "=r"((r)[3]) : "r"(addr))

#define MMA16816(acc, a, b)                                                     \
    asm volatile("mma.sync.aligned.m16n8k16.row.col.f32.f16.f16.f32 "           \
        "{%0,%1,%2,%3}, {%4,%5,%6,%7}, {%8,%9}, {%0,%1,%2,%3};"                 \
        : "+f"((acc)[0]), "+f"((acc)[1]), "+f"((acc)[2]), "+f"((acc)[3])        \
        : "r"((a)[0]), "r"((a)[1]), "r"((a)[2]), "r"((a)[3]),                   \
          "r"((b)[0]), "r"((b)[1]))

#define ROWB 80                       // smem row: 32 halves (64B) + 16B pad

// ---------------------------------------------------------------------------
// init_out: out[b, n, c] = pb[c]  (atomic targets accumulate onto this)
// ---------------------------------------------------------------------------
__global__ void init_out(const float* __restrict__ pb, float* __restrict__ out) {
    size_t idx = (size_t)blockIdx.x * 256 + threadIdx.x;
    if (idx < (size_t)B_ * NODES * C_)
        out[idx] = pb[idx % C_];
}

// ---------------------------------------------------------------------------
// W cast kernel: fp32 -> fp16
// ---------------------------------------------------------------------------
__global__ void wsplit_kernel(const float* __restrict__ W) {
    int i = blockIdx.x * 256 + threadIdx.x;
    g_Wh[i] = __float2half_rn(W[i]);
}

// ---------------------------------------------------------------------------
// Leaves: relu(emb[word]) -> fp16 state + fused projection (direct store)
// ---------------------------------------------------------------------------
__global__ __launch_bounds__(256)
void leaf_kernel(const int* __restrict__ words, const float* __restrict__ emb,
                 const float* __restrict__ P, const float* __restrict__ pb,
                 float* __restrict__ out) {
    __shared__ float Ps[C_ * E_];
    __shared__ float pbs[C_];
    for (int idx = threadIdx.x; idx < C_ * E_; idx += 256) Ps[idx] = P[idx];
    if (threadIdx.x < C_) pbs[threadIdx.x] = pb[threadIdx.x];
    __syncthreads();

    int r    = blockIdx.x * 8 + (threadIdx.x >> 5);
    int lane = threadIdx.x & 31;
    int w = __ldg(&words[r]);
    const float4* src = reinterpret_cast<const float4*>(emb + (size_t)w * E_);
    float4 v0 = src[lane * 2], v1 = src[lane * 2 + 1];
    float x[8] = {fmaxf(v0.x, 0.f), fmaxf(v0.y, 0.f), fmaxf(v0.z, 0.f), fmaxf(v0.w, 0.f),
                  fmaxf(v1.x, 0.f), fmaxf(v1.y, 0.f), fmaxf(v1.z, 0.f), fmaxf(v1.w, 0.f)};
    uint32_t hv[4];
#pragma unroll
    for (int p = 0; p < 4; p++)
        hv[p] = pkh(__float2half_rn(x[2 * p]), __float2half_rn(x[2 * p + 1]));
    int b = r >> 9, i = r & 511;
    size_t off = (size_t)b * SB + (size_t)i * E_ + lane * 8;
    *reinterpret_cast<uint4*>(g_sh + off) = make_uint4(hv[0], hv[1], hv[2], hv[3]);

    float acc[C_];
#pragma unroll
    for (int c = 0; c < C_; c++) {
        const float* pc = &Ps[c * E_ + lane * 8];
        float s = 0.f;
#pragma unroll
        for (int t = 0; t < 8; t++) s = fmaf(x[t], pc[t], s);
        acc[c] = s;
    }
#pragma unroll
    for (int c = 0; c < C_; c++)
#pragma unroll
        for (int o = 16; o > 0; o >>= 1)
            acc[c] += __shfl_xor_sync(0xffffffffu, acc[c], o);
    if (lane == 0) {
        float* orow = out + ((size_t)b * NODES + i) * C_;
#pragma unroll
        for (int c = 0; c < C_; c++) orow[c] = acc[c] + pbs[c];
    }
}

// ---------------------------------------------------------------------------
// Compose GEMM (mma.sync fp16 single product) + fused projection.
// CTA tile BM x 128 (grid.y = 2 covers N=256), 512 threads = 16 warps (4x4),
// warp tile (16*MT) x 32. 4-stage cp.async pipeline over K=512, BK=32.
// ---------------------------------------------------------------------------
template <int BM, int MT, int NCH, int TOTCH, int PLA>
__global__ __launch_bounds__(512, 1)
void mma_gemm(const float* __restrict__ bias, const float* __restrict__ P,
              float* __restrict__ out, int in_off, int out_off, int lg) {
    constexpr int OFF_AH = 0;
    constexpr int OFF_BH = PLA;
    constexpr int STAGE  = PLA + 10240;
    constexpr int SMB    = 4 * STAGE;          // bias: 128 floats
    constexpr int SMP    = SMB + 512;          // P tile: 5 x 128 floats

    extern __shared__ char smem[];
    const uint32_t sb = smem_u32(smem);
    const int tid  = threadIdx.x;
    const int lane = tid & 31;
    const int warp = tid >> 5;
    const int warpM = warp & 3;      // 4 warps over M
    const int warpN = warp >> 2;     // 4 warps over N (32 cols each)
    const int blockRow = blockIdx.x * BM;
    const int colBase  = blockIdx.y * 128;
    const int msk = (1 << lg) - 1;

    if (tid < 128)
        reinterpret_cast<float*>(smem + SMB)[tid] = bias[colBase + tid];
    for (int j = tid; j < C_ * 128; j += 512)
        reinterpret_cast<float*>(smem + SMP)[j] = P[(j >> 7) * E_ + colBase + (j & 127)];

    // --- per-thread cp.async chunk descriptors (<= NCH x 16B per stage) ---
    const __half* srcs[NCH];
    uint32_t dsts[NCH];
#pragma unroll
    for (int j = 0; j < NCH; j++) {
        int c = tid + 512 * j;
        if (c >= TOTCH) c = TOTCH - 1;  // harmless duplicate (guarded at issue)
        if (c < BM * 4) {               // A: BM rows x 64B
            int row = c >> 2, seg = c & 3;
            int gr = blockRow + row, ab = gr >> lg, ai = gr & msk;
            srcs[j] = g_sh + (size_t)ab * SB + (size_t)in_off * E_
                          + (size_t)ai * TWO_E + seg * 8;
            dsts[j] = OFF_AH + row * ROWB + seg * 16;
        } else {                        // B: 128 W-rows x 64B
            int c2 = c - BM * 4;
            int row = c2 >> 2, seg = c2 & 3;
            srcs[j] = g_Wh + (size_t)(colBase + row) * TWO_E + seg * 8;
            dsts[j] = OFF_BH + row * ROWB + seg * 16;
        }
    }

#define ISSUE(it) do {                                              \
        uint32_t _base = sb + ((it) & 3) * STAGE;                   \
        int _k0 = (it) * 32;                                        \
        _Pragma("unroll")                                           \
        for (int _j = 0; _j < NCH; _j++)                            \
            if (tid + 512 * _j < TOTCH)                             \
                CP16(_base + dsts[_j], srcs[_j] + _k0);             \
        CP_COMMIT();                                                \
    } while (0)

    ISSUE(0); ISSUE(1); ISSUE(2);

    float acc[MT][4][4];
#pragma unroll
    for (int mt = 0; mt < MT; mt++)
#pragma unroll
        for (int nt = 0; nt < 4; nt++)
#pragma unroll
            for (int q = 0; q < 4; q++) acc[mt][nt][q] = 0.f;

    const int aRow     = warpM * (16 * MT) + ((lane >> 3) & 1) * 8 + (lane & 7);
    const int aColHalf = (lane >> 4);
    const int bRow     = warpN * 32 + ((lane >> 4) << 3) + (lane & 7);
    const int bColHalf = (lane >> 3) & 1;

    for (int it = 0; it < 16; ++it) {
        if (it <= 13)      asm volatile("cp.async.wait_group 2;" ::: "memory");
        else if (it == 14) asm volatile("cp.async.wait_group 1;" ::: "memory");
        else               asm volatile("cp.async.wait_group 0;" ::: "memory");
        __syncthreads();
        if (it + 3 < 16) ISSUE(it + 3);
        uint32_t base = sb + (it & 3) * STAGE;

#pragma unroll
        for (int kk = 0; kk < 2; kk++) {
            uint32_t Ah[MT][4], Bh[4][2];
#pragma unroll
            for (int mt = 0; mt < MT; mt++) {
                uint32_t addr = base + (uint32_t)((aRow + mt * 16) * ROWB
                              + (kk * 16 + aColHalf * 8) * 2);
                LDSM_X4(Ah[mt], addr + OFF_AH);
            }
#pragma unroll
            for (int ntp = 0; ntp < 2; ntp++) {
                uint32_t addr = base + (uint32_t)((bRow + ntp * 16) * ROWB
                              + (kk * 16 + bColHalf * 8) * 2);
                uint32_t r0[4];
                LDSM_X4(r0, addr + OFF_BH);
                Bh[2 * ntp][0] = r0[0]; Bh[2 * ntp][1] = r0[1];
                Bh[2 * ntp + 1][0] = r0[2]; Bh[2 * ntp + 1][1] = r0[3];
            }
#pragma unroll
            for (int mt = 0; mt < MT; mt++)
#pragma unroll
                for (int nt = 0; nt < 4; nt++)
                    MMA16816(acc[mt][nt], Ah[mt], Bh[nt]);
        }
    }
#undef ISSUE

    // --- epilogue: +bias, relu, fp16 state store, fused partial projection ---
    const float* sbias = reinterpret_cast<const float*>(smem + SMB);
    const float* Ps2   = reinterpret_cast<const float*>(smem + SMP);
    const int nOff = warpN * 32 + (lane & 3) * 2;
#pragma unroll
    for (int mt = 0; mt < MT; mt++) {
#pragma unroll
        for (int h = 0; h < 2; h++) {
            int rl = warpM * (16 * MT) + mt * 16 + (lane >> 2) + 8 * h;
            int gro = blockRow + rl;
            int ob = gro >> lg, oi = gro & msk;
            size_t rowoff = (size_t)ob * SB + (size_t)(out_off + oi) * E_
                          + colBase + nOff;
            uint32_t* dh = reinterpret_cast<uint32_t*>(g_sh + rowoff);
            float p5[C_] = {0.f, 0.f, 0.f, 0.f, 0.f};
#pragma unroll
            for (int nt = 0; nt < 4; nt++) {
                float v0 = fmaxf(acc[mt][nt][2 * h]     + sbias[nOff + nt * 8], 0.f);
                float v1 = fmaxf(acc[mt][nt][2 * h + 1] + sbias[nOff + nt * 8 + 1], 0.f);
                dh[nt * 4] = pkh(__float2half_rn(v0), __float2half_rn(v1));
                int cl = nOff + nt * 8;
#pragma unroll
                for (int c = 0; c < C_; c++)
                    p5[c] += v0 * Ps2[c * 128 + cl] + v1 * Ps2[c * 128 + cl + 1];
            }
#pragma unroll
            for (int c = 0; c < C_; c++) {
                p5[c] += __shfl_xor_sync(0xffffffffu, p5[c], 1);
                p5[c] += __shfl_xor_sync(0xffffffffu, p5[c], 2);
            }
            if ((lane & 3) == 0) {
                float* orow = out + ((size_t)ob * NODES + out_off + oi) * C_;
#pragma unroll
                for (int c = 0; c < C_; c++) atomicAdd(&orow[c], p5[c]);
            }
        }
    }
}

// ---------------------------------------------------------------------------
// Launch
// ---------------------------------------------------------------------------
#define SM128_TOTAL (4 * 20480 + 512 + 2560)   // 85 KB
#define SM64_TOTAL  (4 * 15360 + 512 + 2560)   // 64.5 KB

extern "C" void kernel_launch(void* const* d_in, const int* in_sizes, int n_in,
                              void* d_out, int out_size) {
    const int*   words = (const int*)  d_in[0];
    const float* emb   = (const float*)d_in[1];
    const float* W     = (const float*)d_in[2];
    const float* bias  = (const float*)d_in[3];
    const float* P     = (const float*)d_in[4];
    const float* pb    = (const float*)d_in[5];
    float*       out   = (float*)d_out;

    static bool attr_done = false;
    if (!attr_done) {
        cudaFuncSetAttribute((const void*)mma_gemm<128, 2, 2, 1024, 10240>,
                             cudaFuncAttributeMaxDynamicSharedMemorySize, SM128_TOTAL);
        cudaFuncSetAttribute((const void*)mma_gemm<64, 1, 2, 768, 5120>,
                             cudaFuncAttributeMaxDynamicSharedMemorySize, SM64_TOTAL);
        attr_done = true;
    }

    init_out<<<(B_ * NODES * C_ + 255) / 256, 256>>>(pb, out);
    wsplit_kernel<<<(E_ * TWO_E) / 256, 256>>>(W);
    leaf_kernel<<<(B_ * L_) / 8, 256>>>(words, emb, P, pb, out);

    int off = 0, n = L_;
    for (int l = 0; l < 9; l++) {
        int rpb = n >> 1;
        int lg  = 8 - l;
        int M   = B_ * rpb;
        if (l < 4) {
            dim3 grid(M / 128, 2);
            mma_gemm<128, 2, 2, 1024, 10240><<<grid, 512, SM128_TOTAL>>>(
                bias, P, out, off, off + n, lg);
        } else {
            dim3 grid(M / 64, 2);
            mma_gemm<64, 1, 2, 768, 5120><<<grid, 512, SM64_TOTAL>>>(
                bias, P, out, off, off + n, lg);
        }
        off += n;
        n >>= 1;
    }
}